// round 1
// baseline (speedup 1.0000x reference)
#include <cuda_runtime.h>
#include <math.h>

#define EMBED   768
#define HEADS   8
#define HDIM    96
#define DEPTH   12
#define MLPH    3072
#define NP      1568
#define BATCH   2
#define NTOK    (BATCH*NP)      // 3136
#define KPATCH  1536            // 3*2*16*16

// ---------------- scratch (device globals: allocation-free) ----------------
__device__ float  g_im2col[NTOK*KPATCH];          // 19.3 MB
__device__ float  g_h    [NTOK*EMBED];            // residual stream
__device__ float  g_y    [NTOK*EMBED];            // LN output
__device__ float  g_qkv  [NTOK*3*EMBED];          // 28.9 MB
__device__ float  g_attn [39337984];              // 2*8*1568*1568 = 157 MB
__device__ float  g_ao   [NTOK*EMBED];            // attention out
__device__ float  g_mlp  [NTOK*MLPH];             // 38.5 MB
__device__ float  g_pool [BATCH*EMBED];
__device__ float  g_pln  [BATCH*EMBED];
__device__ double g_freq [EMBED/2];

// ---------------- generic tiled SGEMM ----------------
// C[m,n] = sum_k A[m,k]*B(k,n) (+bias)(+gelu)(+residual)
// A row-major [M,K] (k contiguous), lda = row stride.
// BT=true : B is [N,K] row-major (weights, k contiguous)  -> B[n*ldb+k]
// BT=false: B is [K,N] row-major (n contiguous)           -> B[k*ldb+n]
// Batched over gridDim.z: z -> (b = z/H, h = z%H), pointer offsets via strides.
// Requirements: K%8==0, N%4==0 (for BT=false vector loads), 16B-aligned bases/strides.
// EPI: 0 none | 1 +bias | 2 +bias,gelu(erf) | 4 +bias,+residual
template<int BM,int BN,int BK,int TM,int TN,bool BT,int EPI>
__global__ void __launch_bounds__((BM/TM)*(BN/TN))
gemm_kernel(const float* __restrict__ A, const float* __restrict__ Bm,
            const float* __restrict__ bias, const float* __restrict__ R,
            float* __restrict__ Cm,
            int M, int N, int K, int lda, int ldb, int ldc, int ldr,
            long long sAb, long long sAh, long long sBb, long long sBh,
            long long sCb, long long sCh, long long sRb, long long sRh, int H)
{
    constexpr int NT = (BM/TM)*(BN/TN);
    const int z  = blockIdx.z;
    const int bb = z / H, hh = z % H;
    A  += bb*sAb + hh*sAh;
    Bm += bb*sBb + hh*sBh;
    Cm += bb*sCb + hh*sCh;
    if (EPI >= 3) R += bb*sRb + hh*sRh;

    __shared__ __align__(16) float As[BK][BM];
    __shared__ __align__(16) float Bs[BK][BN];

    const int tid = threadIdx.x;
    const int tx  = tid % (BN/TN);
    const int ty  = tid / (BN/TN);
    const int m0  = blockIdx.y * BM;
    const int n0  = blockIdx.x * BN;

    float acc[TM][TN];
    #pragma unroll
    for (int i = 0; i < TM; i++)
        #pragma unroll
        for (int j = 0; j < TN; j++) acc[i][j] = 0.f;

    for (int k0 = 0; k0 < K; k0 += BK) {
        // ---- load A tile (BM x BK), float4 along k, store transposed
        constexpr int AV = BM*BK/4;
        #pragma unroll
        for (int i = tid; i < AV; i += NT) {
            int row = i / (BK/4);
            int c4  = (i % (BK/4)) * 4;
            float4 v = make_float4(0.f,0.f,0.f,0.f);
            if (m0 + row < M)
                v = *(const float4*)&A[(long long)(m0+row)*lda + k0 + c4];
            As[c4+0][row]=v.x; As[c4+1][row]=v.y; As[c4+2][row]=v.z; As[c4+3][row]=v.w;
        }
        // ---- load B tile
        if (BT) {
            constexpr int BV = BN*BK/4;
            #pragma unroll
            for (int i = tid; i < BV; i += NT) {
                int row = i / (BK/4);
                int c4  = (i % (BK/4)) * 4;
                float4 v = make_float4(0.f,0.f,0.f,0.f);
                if (n0 + row < N)
                    v = *(const float4*)&Bm[(long long)(n0+row)*ldb + k0 + c4];
                Bs[c4+0][row]=v.x; Bs[c4+1][row]=v.y; Bs[c4+2][row]=v.z; Bs[c4+3][row]=v.w;
            }
        } else {
            constexpr int BV = BK*BN/4;
            #pragma unroll
            for (int i = tid; i < BV; i += NT) {
                int kr = i / (BN/4);
                int c4 = (i % (BN/4)) * 4;
                float4 v = make_float4(0.f,0.f,0.f,0.f);
                if (n0 + c4 < N)
                    v = *(const float4*)&Bm[(long long)(k0+kr)*ldb + n0 + c4];
                *(float4*)&Bs[kr][c4] = v;
            }
        }
        __syncthreads();
        #pragma unroll
        for (int kk = 0; kk < BK; kk++) {
            float ra[TM], rb[TN];
            #pragma unroll
            for (int i = 0; i < TM; i += 4)
                *(float4*)&ra[i] = *(const float4*)&As[kk][ty*TM + i];
            #pragma unroll
            for (int j = 0; j < TN; j += 4)
                *(float4*)&rb[j] = *(const float4*)&Bs[kk][tx*TN + j];
            #pragma unroll
            for (int i = 0; i < TM; i++)
                #pragma unroll
                for (int j = 0; j < TN; j++)
                    acc[i][j] = fmaf(ra[i], rb[j], acc[i][j]);
        }
        __syncthreads();
    }

    #pragma unroll
    for (int i = 0; i < TM; i++) {
        int m = m0 + ty*TM + i;
        if (m >= M) continue;
        #pragma unroll
        for (int j = 0; j < TN; j++) {
            int n = n0 + tx*TN + j;
            if (n >= N) continue;
            float v = acc[i][j];
            if (EPI == 1 || EPI == 2 || EPI == 4) v += bias[n];
            if (EPI == 2) v = 0.5f * v * (1.0f + erff(v * 0.70710678118654752f));
            if (EPI >= 3) v += R[(long long)m*ldr + n];
            Cm[(long long)m*ldc + n] = v;
        }
    }
}

// ---------------- layernorm: one block (256 thr) per row ----------------
__global__ void ln_kernel(const float* __restrict__ X, const float* __restrict__ sc,
                          const float* __restrict__ bi, float* __restrict__ Y, int Cn)
{
    const float* x = X + (long long)blockIdx.x * Cn;
    float*       y = Y + (long long)blockIdx.x * Cn;
    __shared__ float sh1[32], sh2[32];
    int tid = threadIdx.x;
    float s = 0.f, s2 = 0.f;
    for (int i = tid; i < Cn; i += 256) { float v = x[i]; s += v; s2 += v*v; }
    #pragma unroll
    for (int o = 16; o > 0; o >>= 1) {
        s  += __shfl_xor_sync(0xffffffffu, s,  o);
        s2 += __shfl_xor_sync(0xffffffffu, s2, o);
    }
    if ((tid & 31) == 0) { sh1[tid>>5] = s; sh2[tid>>5] = s2; }
    __syncthreads();
    if (tid < 32) {
        float a = (tid < 8) ? sh1[tid] : 0.f;
        float b = (tid < 8) ? sh2[tid] : 0.f;
        #pragma unroll
        for (int o = 4; o > 0; o >>= 1) {
            a += __shfl_xor_sync(0xffffffffu, a, o);
            b += __shfl_xor_sync(0xffffffffu, b, o);
        }
        if (tid == 0) { sh1[0] = a; sh2[0] = b; }
    }
    __syncthreads();
    float mean = sh1[0] / Cn;
    float var  = sh2[0] / Cn - mean*mean;
    float inv  = rsqrtf(var + 1e-5f);
    for (int i = tid; i < Cn; i += 256)
        y[i] = (x[i] - mean) * inv * sc[i] + bi[i];
}

// ---------------- softmax over rows of length NP (register-cached) ----------------
__global__ void softmax_kernel(float* __restrict__ S)
{
    float* p = S + (long long)blockIdx.x * NP;
    __shared__ float sh[32];
    int tid = threadIdx.x;
    const int IT = (NP + 255) / 256;   // 7
    float vals[(NP + 255) / 256];
    float mx = -1e30f;
    #pragma unroll
    for (int it = 0; it < IT; it++) {
        int i = tid + it*256;
        float v = (i < NP) ? p[i] : -1e30f;
        vals[it] = v;
        mx = fmaxf(mx, v);
    }
    #pragma unroll
    for (int o = 16; o > 0; o >>= 1) mx = fmaxf(mx, __shfl_xor_sync(0xffffffffu, mx, o));
    if ((tid & 31) == 0) sh[tid>>5] = mx;
    __syncthreads();
    if (tid < 32) {
        float v = (tid < 8) ? sh[tid] : -1e30f;
        #pragma unroll
        for (int o = 4; o > 0; o >>= 1) v = fmaxf(v, __shfl_xor_sync(0xffffffffu, v, o));
        if (tid == 0) sh[0] = v;
    }
    __syncthreads();
    mx = sh[0];
    __syncthreads();
    float sum = 0.f;
    #pragma unroll
    for (int it = 0; it < IT; it++) {
        int i = tid + it*256;
        float e = (i < NP) ? expf(vals[it] - mx) : 0.f;
        vals[it] = e;
        sum += e;
    }
    #pragma unroll
    for (int o = 16; o > 0; o >>= 1) sum += __shfl_xor_sync(0xffffffffu, sum, o);
    if ((tid & 31) == 0) sh[tid>>5] = sum;
    __syncthreads();
    if (tid < 32) {
        float v = (tid < 8) ? sh[tid] : 0.f;
        #pragma unroll
        for (int o = 4; o > 0; o >>= 1) v += __shfl_xor_sync(0xffffffffu, v, o);
        if (tid == 0) sh[0] = v;
    }
    __syncthreads();
    float inv = 1.0f / sh[0];
    #pragma unroll
    for (int it = 0; it < IT; it++) {
        int i = tid + it*256;
        if (i < NP) p[i] = vals[it] * inv;
    }
}

// ---------------- im2col for tubelet conv (stride==kernel==(2,16,16)) ----------------
__global__ void im2col_kernel(const float* __restrict__ x)
{
    long long idx = (long long)blockIdx.x * 256 + threadIdx.x;
    if (idx >= (long long)NTOK * KPATCH) return;
    int j = (int)(idx % KPATCH);
    int m = (int)(idx / KPATCH);
    int b = m / NP, n = m % NP;
    int t = n / 196, r = n % 196, yy = r / 14, xx = r % 14;
    int i  = j / 512, r2 = j % 512;
    int dt = r2 / 256, r3 = r2 % 256;
    int dy = r3 / 16,  dx = r3 % 16;
    long long off = ((((long long)(b*3 + i)*16 + (2*t + dt))*224) + (16*yy + dy))*224 + (16*xx + dx);
    g_im2col[idx] = x[off];
}

// ---------------- positional encoding ----------------
__global__ void freq_kernel()
{
    int c2 = threadIdx.x;
    if (c2 < EMBED/2) g_freq[c2] = pow(10000.0, -2.0 * c2 / (double)EMBED);
}
__global__ void posadd_kernel()
{
    int idx = blockIdx.x * 256 + threadIdx.x;
    if (idx >= NP*EMBED) return;
    int n = idx / EMBED, c = idx % EMBED;
    double a = (double)n * g_freq[c >> 1];
    float v = (c & 1) ? (float)cos(a) : (float)sin(a);
    g_h[idx]            += v;
    g_h[idx + NP*EMBED] += v;   // batch 1
}

// ---------------- mean pool over tokens ----------------
__global__ void pool_kernel()
{
    int idx = blockIdx.x * 256 + threadIdx.x;
    if (idx >= BATCH*EMBED) return;
    int b = idx / EMBED, c = idx % EMBED;
    const float* base = g_h + (long long)b*NP*EMBED + c;
    float s = 0.f;
    for (int n = 0; n < NP; n++) s += base[(long long)n*EMBED];
    g_pool[idx] = s * (1.0f / NP);
}

// ---------------- classifier head: one warp per (b, class) ----------------
__global__ void head_kernel(const float* __restrict__ W, const float* __restrict__ hb,
                            float* __restrict__ out)
{
    int g = blockIdx.x * 256 + threadIdx.x;
    int warp = g >> 5, lane = g & 31;
    if (warp >= BATCH*1000) return;
    int b = warp / 1000, j = warp % 1000;
    float s = 0.f;
    for (int c = lane; c < EMBED; c += 32)
        s += g_pln[b*EMBED + c] * W[j*EMBED + c];
    #pragma unroll
    for (int o = 16; o > 0; o >>= 1) s += __shfl_xor_sync(0xffffffffu, s, o);
    if (lane == 0) out[warp] = s + hb[j];
}

// ---------------- host orchestration ----------------
extern "C" void kernel_launch(void* const* d_in, const int* in_sizes, int n_in,
                              void* d_out, int out_size)
{
    const float* x      = (const float*)d_in[0];
    const float* conv_w = (const float*)d_in[1];
    const float* conv_b = (const float*)d_in[2];
    const float* n1s    = (const float*)d_in[3];
    const float* n1b    = (const float*)d_in[4];
    const float* qkv_w  = (const float*)d_in[5];
    const float* out_w  = (const float*)d_in[6];
    const float* out_b  = (const float*)d_in[7];
    const float* n2s    = (const float*)d_in[8];
    const float* n2b    = (const float*)d_in[9];
    const float* fc1_w  = (const float*)d_in[10];
    const float* fc1_b  = (const float*)d_in[11];
    const float* fc2_w  = (const float*)d_in[12];
    const float* fc2_b  = (const float*)d_in[13];
    const float* fns    = (const float*)d_in[14];
    const float* fnb    = (const float*)d_in[15];
    const float* head_w = (const float*)d_in[16];
    const float* head_b = (const float*)d_in[17];
    float* out = (float*)d_out;

    float *im2col, *h, *y, *qkv, *attn, *ao, *mlp, *pool, *pln;
    cudaGetSymbolAddress((void**)&im2col, g_im2col);
    cudaGetSymbolAddress((void**)&h,      g_h);
    cudaGetSymbolAddress((void**)&y,      g_y);
    cudaGetSymbolAddress((void**)&qkv,    g_qkv);
    cudaGetSymbolAddress((void**)&attn,   g_attn);
    cudaGetSymbolAddress((void**)&ao,     g_ao);
    cudaGetSymbolAddress((void**)&mlp,    g_mlp);
    cudaGetSymbolAddress((void**)&pool,   g_pool);
    cudaGetSymbolAddress((void**)&pln,    g_pln);

    const long long Z0 = 0;

    // ---- patch embed ----
    im2col_kernel<<<(int)(((long long)NTOK*KPATCH + 255)/256), 256>>>(x);
    {   // h = im2col @ conv_w^T + conv_b
        dim3 g((EMBED+127)/128, (NTOK+127)/128, 1);
        gemm_kernel<128,128,8,8,8,true,1><<<g,256>>>(
            im2col, conv_w, conv_b, nullptr, h,
            NTOK, EMBED, KPATCH, KPATCH, KPATCH, EMBED, 0,
            Z0,Z0,Z0,Z0,Z0,Z0,Z0,Z0, 1);
    }
    freq_kernel<<<1, EMBED/2>>>();
    posadd_kernel<<<(NP*EMBED + 255)/256, 256>>>();

    // ---- transformer blocks ----
    for (int l = 0; l < DEPTH; l++) {
        const float* qw = qkv_w + (long long)l*3*EMBED*EMBED;
        const float* ow = out_w + (long long)l*EMBED*EMBED;
        const float* ob = out_b + (long long)l*EMBED;
        const float* w1 = fc1_w + (long long)l*MLPH*EMBED;
        const float* b1 = fc1_b + (long long)l*MLPH;
        const float* w2 = fc2_w + (long long)l*EMBED*MLPH;
        const float* b2 = fc2_b + (long long)l*EMBED;

        // y = LN1(h)
        ln_kernel<<<NTOK,256>>>(h, n1s + l*EMBED, n1b + l*EMBED, y, EMBED);

        // qkv = y @ qw^T
        {
            dim3 g((3*EMBED+127)/128, (NTOK+127)/128, 1);
            gemm_kernel<128,128,8,8,8,true,0><<<g,256>>>(
                y, qw, nullptr, nullptr, qkv,
                NTOK, 3*EMBED, EMBED, EMBED, EMBED, 3*EMBED, 0,
                Z0,Z0,Z0,Z0,Z0,Z0,Z0,Z0, 1);
        }

        // S[b,h] = Q @ K^T   (M=N=1568, K=96), batched z = b*H + h
        {
            dim3 g((NP+127)/128, (NP+127)/128, BATCH*HEADS);
            gemm_kernel<128,128,8,8,8,true,0><<<g,256>>>(
                qkv /*Q*/, qkv + EMBED /*K*/, nullptr, nullptr, attn,
                NP, NP, HDIM, 3*EMBED, 3*EMBED, NP, 0,
                (long long)NP*3*EMBED, (long long)HDIM,
                (long long)NP*3*EMBED, (long long)HDIM,
                (long long)HEADS*NP*NP, (long long)NP*NP,
                Z0, Z0, HEADS);
        }

        softmax_kernel<<<BATCH*HEADS*NP, 256>>>(attn);

        // O[b,h] = P @ V    (M=1568, N=96, K=1568), B in [K,N] layout
        {
            dim3 g(HDIM/32, (NP+127)/128, BATCH*HEADS);
            gemm_kernel<128,32,8,8,4,false,0><<<g,128>>>(
                attn, qkv + 2*EMBED /*V*/, nullptr, nullptr, ao,
                NP, HDIM, NP, NP, 3*EMBED, EMBED, 0,
                (long long)HEADS*NP*NP, (long long)NP*NP,
                (long long)NP*3*EMBED, (long long)HDIM,
                (long long)NP*EMBED, (long long)HDIM,
                Z0, Z0, HEADS);
        }

        // h = h + ao @ ow^T + ob
        {
            dim3 g((EMBED+127)/128, (NTOK+127)/128, 1);
            gemm_kernel<128,128,8,8,8,true,4><<<g,256>>>(
                ao, ow, ob, h, h,
                NTOK, EMBED, EMBED, EMBED, EMBED, EMBED, EMBED,
                Z0,Z0,Z0,Z0,Z0,Z0,Z0,Z0, 1);
        }

        // y = LN2(h)
        ln_kernel<<<NTOK,256>>>(h, n2s + l*EMBED, n2b + l*EMBED, y, EMBED);

        // mlp = gelu(y @ w1^T + b1)
        {
            dim3 g((MLPH+127)/128, (NTOK+127)/128, 1);
            gemm_kernel<128,128,8,8,8,true,2><<<g,256>>>(
                y, w1, b1, nullptr, mlp,
                NTOK, MLPH, EMBED, EMBED, EMBED, MLPH, 0,
                Z0,Z0,Z0,Z0,Z0,Z0,Z0,Z0, 1);
        }

        // h = h + mlp @ w2^T + b2
        {
            dim3 g((EMBED+127)/128, (NTOK+127)/128, 1);
            gemm_kernel<128,128,8,8,8,true,4><<<g,256>>>(
                mlp, w2, b2, h, h,
                NTOK, EMBED, MLPH, MLPH, MLPH, EMBED, EMBED,
                Z0,Z0,Z0,Z0,Z0,Z0,Z0,Z0, 1);
        }
    }

    // ---- pooled head ----
    pool_kernel<<<(BATCH*EMBED + 255)/256, 256>>>();
    ln_kernel<<<BATCH,256>>>(pool, fns, fnb, pln, EMBED);
    head_kernel<<<(BATCH*1000*32 + 255)/256, 256>>>(head_w, head_b, out);
}

// round 2
// speedup vs baseline: 2.4230x; 2.4230x over previous
#include <cuda_runtime.h>
#include <cuda_bf16.h>
#include <math.h>
#include <stdint.h>

#define EMBED   768
#define HEADS   8
#define HDIM    96
#define DEPTH   12
#define MLPH    3072
#define NP      1568
#define BATCH   2
#define NTOK    (BATCH*NP)      // 3136
#define KPATCH  1536            // 3*2*16*16

// ---------------- scratch (device globals: allocation-free) ----------------
__device__ float  g_im2col[NTOK*KPATCH];          // 19.3 MB
__device__ float  g_h    [NTOK*EMBED];            // residual stream
__device__ float  g_y    [NTOK*EMBED];            // LN output
__device__ float  g_qkv  [NTOK*3*EMBED];          // 28.9 MB
__device__ float  g_attn [39337984];              // 2*8*1568*1568 = 157 MB
__device__ float  g_ao   [NTOK*EMBED];            // attention out
__device__ float  g_mlp  [NTOK*MLPH];             // 38.5 MB
__device__ float  g_pool [BATCH*EMBED];
__device__ float  g_pln  [BATCH*EMBED];
__device__ double g_freq [EMBED/2];

// ================= tensor-core GEMM (bf16 split, fp32-accurate) ============
// C[m,n] = sum_k A[m,k]*B(k,n) (+bias)(+gelu)(+residual)
// A row-major [M,K]. BT=true: B[N][K] (weights). BT=false: B[K][N].
// Split each fp32 into bf16 hi+lo; compute Ah*Bh + Ah*Bl + Al*Bh.
// Tiles: BM=128 BN=64 BK=32, 256 threads = 8 warps (4m x 2n), warp = 32x32.
// EPI: 0 none | 1 +bias | 2 +bias,gelu(erf) | 4 +bias,+residual

#define SA 40   // smem row stride in bf16 elements (padding -> conflict-free ldmatrix)

#define LDSM4(R, addr) \
    asm volatile("ldmatrix.sync.aligned.m8n8.x4.shared.b16 {%0,%1,%2,%3},[%4];" \
        : "=r"((R)[0]), "=r"((R)[1]), "=r"((R)[2]), "=r"((R)[3]) : "r"(addr))

#define MMA16816(C, A, B0, B1) \
    asm volatile("mma.sync.aligned.m16n8k16.row.col.f32.bf16.bf16.f32 " \
        "{%0,%1,%2,%3},{%4,%5,%6,%7},{%8,%9},{%0,%1,%2,%3};" \
        : "+f"((C)[0]), "+f"((C)[1]), "+f"((C)[2]), "+f"((C)[3]) \
        : "r"((A)[0]), "r"((A)[1]), "r"((A)[2]), "r"((A)[3]), "r"(B0), "r"(B1))

__device__ __forceinline__ void split_bf16(float v, __nv_bfloat16& h, __nv_bfloat16& l)
{
    h = __float2bfloat16(v);
    l = __float2bfloat16(v - __bfloat162float(h));
}

template<int EPI, bool BT>
__global__ void __launch_bounds__(256, 2)
mma_gemm(const float* __restrict__ A, const float* __restrict__ Bm,
         const float* __restrict__ bias, const float* __restrict__ R,
         float* __restrict__ Cm,
         int M, int N, int K, int lda, int ldb, int ldc, int ldr,
         long long sAb, long long sAh_, long long sBb, long long sBh_,
         long long sCb, long long sCh_, long long sRb, long long sRh_, int H)
{
    const int z  = blockIdx.z;
    const int bb = z / H, hh = z % H;
    A  += bb*sAb + hh*sAh_;
    Bm += bb*sBb + hh*sBh_;
    Cm += bb*sCb + hh*sCh_;
    if (EPI >= 3) R += bb*sRb + hh*sRh_;

    __shared__ __align__(16) __nv_bfloat16 sAhM[128*SA];
    __shared__ __align__(16) __nv_bfloat16 sAlM[128*SA];
    __shared__ __align__(16) __nv_bfloat16 sBhM[64*SA];
    __shared__ __align__(16) __nv_bfloat16 sBlM[64*SA];

    const int tid  = threadIdx.x;
    const int lane = tid & 31;
    const int w    = tid >> 5;
    const int wm   = w >> 1;        // 0..3
    const int wn   = w & 1;         // 0..1
    const int m0   = blockIdx.y * 128;
    const int n0   = blockIdx.x * 64;

    float c[2][4][4];
    #pragma unroll
    for (int i = 0; i < 2; i++)
        #pragma unroll
        for (int j = 0; j < 4; j++)
            #pragma unroll
            for (int q = 0; q < 4; q++) c[i][j][q] = 0.f;

    // per-lane ldmatrix offsets: row = lane&15, col-half = (lane>>4)*8
    const int lrow = lane & 15;
    const int lcol = (lane >> 4) * 8;
    const uint32_t aoff = (uint32_t)(((wm*32 + lrow)*SA + lcol) * 2);
    const uint32_t boff = (uint32_t)(((wn*32 + lrow)*SA + lcol) * 2);
    const uint32_t aH = (uint32_t)__cvta_generic_to_shared(sAhM) + aoff;
    const uint32_t aL = (uint32_t)__cvta_generic_to_shared(sAlM) + aoff;
    const uint32_t bH = (uint32_t)__cvta_generic_to_shared(sBhM) + boff;
    const uint32_t bL = (uint32_t)__cvta_generic_to_shared(sBlM) + boff;

    float4 avr[4];
    float4 bvr[2];

    const int T = K / 32;

    // ---- gmem staging loads for tile at k0 ----
    auto loadA = [&](int k0) {
        #pragma unroll
        for (int i = 0; i < 4; i++) {
            int slot = tid + i*256;
            int row  = slot >> 3;
            int kc   = (slot & 7) << 2;
            avr[i] = make_float4(0.f,0.f,0.f,0.f);
            if (m0 + row < M)
                avr[i] = *(const float4*)&A[(long long)(m0+row)*lda + k0 + kc];
        }
    };
    auto loadB = [&](int k0) {
        #pragma unroll
        for (int i = 0; i < 2; i++) {
            int slot = tid + i*256;
            bvr[i] = make_float4(0.f,0.f,0.f,0.f);
            if (BT) {
                int row = slot >> 3;
                int kc  = (slot & 7) << 2;
                if (n0 + row < N)
                    bvr[i] = *(const float4*)&Bm[(long long)(n0+row)*ldb + k0 + kc];
            } else {
                int kr = slot >> 4;
                int nc = (slot & 15) << 2;
                if (n0 + nc < N)
                    bvr[i] = *(const float4*)&Bm[(long long)(k0+kr)*ldb + n0 + nc];
            }
        }
    };

    auto storeTiles = [&]() {
        #pragma unroll
        for (int i = 0; i < 4; i++) {
            int slot = tid + i*256;
            int row  = slot >> 3;
            int kc   = (slot & 7) << 2;
            __nv_bfloat16 h0,h1,h2,h3,l0,l1,l2,l3;
            split_bf16(avr[i].x, h0, l0); split_bf16(avr[i].y, h1, l1);
            split_bf16(avr[i].z, h2, l2); split_bf16(avr[i].w, h3, l3);
            __nv_bfloat162 p;
            p.x=h0; p.y=h1; *(__nv_bfloat162*)&sAhM[row*SA+kc  ] = p;
            p.x=h2; p.y=h3; *(__nv_bfloat162*)&sAhM[row*SA+kc+2] = p;
            p.x=l0; p.y=l1; *(__nv_bfloat162*)&sAlM[row*SA+kc  ] = p;
            p.x=l2; p.y=l3; *(__nv_bfloat162*)&sAlM[row*SA+kc+2] = p;
        }
        #pragma unroll
        for (int i = 0; i < 2; i++) {
            int slot = tid + i*256;
            __nv_bfloat16 h0,h1,h2,h3,l0,l1,l2,l3;
            split_bf16(bvr[i].x, h0, l0); split_bf16(bvr[i].y, h1, l1);
            split_bf16(bvr[i].z, h2, l2); split_bf16(bvr[i].w, h3, l3);
            if (BT) {
                int row = slot >> 3;
                int kc  = (slot & 7) << 2;
                __nv_bfloat162 p;
                p.x=h0; p.y=h1; *(__nv_bfloat162*)&sBhM[row*SA+kc  ] = p;
                p.x=h2; p.y=h3; *(__nv_bfloat162*)&sBhM[row*SA+kc+2] = p;
                p.x=l0; p.y=l1; *(__nv_bfloat162*)&sBlM[row*SA+kc  ] = p;
                p.x=l2; p.y=l3; *(__nv_bfloat162*)&sBlM[row*SA+kc+2] = p;
            } else {
                int kr = slot >> 4;
                int nc = (slot & 15) << 2;
                sBhM[(nc+0)*SA+kr]=h0; sBhM[(nc+1)*SA+kr]=h1;
                sBhM[(nc+2)*SA+kr]=h2; sBhM[(nc+3)*SA+kr]=h3;
                sBlM[(nc+0)*SA+kr]=l0; sBlM[(nc+1)*SA+kr]=l1;
                sBlM[(nc+2)*SA+kr]=l2; sBlM[(nc+3)*SA+kr]=l3;
            }
        }
    };

    loadA(0); loadB(0);

    for (int t = 0; t < T; t++) {
        storeTiles();
        __syncthreads();
        if (t + 1 < T) { loadA((t+1)*32); loadB((t+1)*32); }

        #pragma unroll
        for (int kk2 = 0; kk2 < 2; kk2++) {
            const uint32_t kb = (uint32_t)(kk2 * 16 * 2);   // byte offset along k
            uint32_t Ah[2][4], Al[2][4], Bh[2][4], Bl[2][4];
            #pragma unroll
            for (int mi = 0; mi < 2; mi++) {
                LDSM4(Ah[mi], aH + (uint32_t)(mi*16*SA*2) + kb);
                LDSM4(Al[mi], aL + (uint32_t)(mi*16*SA*2) + kb);
            }
            #pragma unroll
            for (int pr = 0; pr < 2; pr++) {
                LDSM4(Bh[pr], bH + (uint32_t)(pr*16*SA*2) + kb);
                LDSM4(Bl[pr], bL + (uint32_t)(pr*16*SA*2) + kb);
            }
            #pragma unroll
            for (int mi = 0; mi < 2; mi++) {
                #pragma unroll
                for (int pr = 0; pr < 2; pr++) {
                    // nf = pr*2 + 0 : regs {r0, r2};  nf = pr*2 + 1 : regs {r1, r3}
                    MMA16816(c[mi][pr*2  ], Ah[mi], Bh[pr][0], Bh[pr][2]);
                    MMA16816(c[mi][pr*2  ], Ah[mi], Bl[pr][0], Bl[pr][2]);
                    MMA16816(c[mi][pr*2  ], Al[mi], Bh[pr][0], Bh[pr][2]);
                    MMA16816(c[mi][pr*2+1], Ah[mi], Bh[pr][1], Bh[pr][3]);
                    MMA16816(c[mi][pr*2+1], Ah[mi], Bl[pr][1], Bl[pr][3]);
                    MMA16816(c[mi][pr*2+1], Al[mi], Bh[pr][1], Bh[pr][3]);
                }
            }
        }
        __syncthreads();
    }

    // ---------------- epilogue ----------------
    const int g  = lane >> 2;
    const int tq = lane & 3;
    #pragma unroll
    for (int mi = 0; mi < 2; mi++) {
        #pragma unroll
        for (int nf = 0; nf < 4; nf++) {
            int col = n0 + wn*32 + nf*8 + tq*2;
            #pragma unroll
            for (int half = 0; half < 2; half++) {
                int row = m0 + wm*32 + mi*16 + g + half*8;
                if (row >= M || col >= N) continue;
                float v0 = c[mi][nf][half*2 + 0];
                float v1 = c[mi][nf][half*2 + 1];
                if (EPI == 1 || EPI == 2 || EPI == 4) { v0 += bias[col]; v1 += bias[col+1]; }
                if (EPI == 2) {
                    v0 = 0.5f * v0 * (1.0f + erff(v0 * 0.70710678118654752f));
                    v1 = 0.5f * v1 * (1.0f + erff(v1 * 0.70710678118654752f));
                }
                if (EPI >= 3) {
                    float2 r2 = *(const float2*)&R[(long long)row*ldr + col];
                    v0 += r2.x; v1 += r2.y;
                }
                float2 o; o.x = v0; o.y = v1;
                *(float2*)&Cm[(long long)row*ldc + col] = o;
            }
        }
    }
}

// ---------------- layernorm: one block (256 thr) per row ----------------
__global__ void ln_kernel(const float* __restrict__ X, const float* __restrict__ sc,
                          const float* __restrict__ bi, float* __restrict__ Y, int Cn)
{
    const float* x = X + (long long)blockIdx.x * Cn;
    float*       y = Y + (long long)blockIdx.x * Cn;
    __shared__ float sh1[32], sh2[32];
    int tid = threadIdx.x;
    float s = 0.f, s2 = 0.f;
    for (int i = tid; i < Cn; i += 256) { float v = x[i]; s += v; s2 += v*v; }
    #pragma unroll
    for (int o = 16; o > 0; o >>= 1) {
        s  += __shfl_xor_sync(0xffffffffu, s,  o);
        s2 += __shfl_xor_sync(0xffffffffu, s2, o);
    }
    if ((tid & 31) == 0) { sh1[tid>>5] = s; sh2[tid>>5] = s2; }
    __syncthreads();
    if (tid < 32) {
        float a = (tid < 8) ? sh1[tid] : 0.f;
        float b = (tid < 8) ? sh2[tid] : 0.f;
        #pragma unroll
        for (int o = 4; o > 0; o >>= 1) {
            a += __shfl_xor_sync(0xffffffffu, a, o);
            b += __shfl_xor_sync(0xffffffffu, b, o);
        }
        if (tid == 0) { sh1[0] = a; sh2[0] = b; }
    }
    __syncthreads();
    float mean = sh1[0] / Cn;
    float var  = sh2[0] / Cn - mean*mean;
    float inv  = rsqrtf(var + 1e-5f);
    for (int i = tid; i < Cn; i += 256)
        y[i] = (x[i] - mean) * inv * sc[i] + bi[i];
}

// ---------------- softmax over rows of length NP (register-cached) ----------------
__global__ void softmax_kernel(float* __restrict__ S)
{
    float* p = S + (long long)blockIdx.x * NP;
    __shared__ float sh[32];
    int tid = threadIdx.x;
    const int IT = (NP + 255) / 256;   // 7
    float vals[(NP + 255) / 256];
    float mx = -1e30f;
    #pragma unroll
    for (int it = 0; it < IT; it++) {
        int i = tid + it*256;
        float v = (i < NP) ? p[i] : -1e30f;
        vals[it] = v;
        mx = fmaxf(mx, v);
    }
    #pragma unroll
    for (int o = 16; o > 0; o >>= 1) mx = fmaxf(mx, __shfl_xor_sync(0xffffffffu, mx, o));
    if ((tid & 31) == 0) sh[tid>>5] = mx;
    __syncthreads();
    if (tid < 32) {
        float v = (tid < 8) ? sh[tid] : -1e30f;
        #pragma unroll
        for (int o = 4; o > 0; o >>= 1) v = fmaxf(v, __shfl_xor_sync(0xffffffffu, v, o));
        if (tid == 0) sh[0] = v;
    }
    __syncthreads();
    mx = sh[0];
    __syncthreads();
    float sum = 0.f;
    #pragma unroll
    for (int it = 0; it < IT; it++) {
        int i = tid + it*256;
        float e = (i < NP) ? expf(vals[it] - mx) : 0.f;
        vals[it] = e;
        sum += e;
    }
    #pragma unroll
    for (int o = 16; o > 0; o >>= 1) sum += __shfl_xor_sync(0xffffffffu, sum, o);
    if ((tid & 31) == 0) sh[tid>>5] = sum;
    __syncthreads();
    if (tid < 32) {
        float v = (tid < 8) ? sh[tid] : 0.f;
        #pragma unroll
        for (int o = 4; o > 0; o >>= 1) v += __shfl_xor_sync(0xffffffffu, v, o);
        if (tid == 0) sh[0] = v;
    }
    __syncthreads();
    float inv = 1.0f / sh[0];
    #pragma unroll
    for (int it = 0; it < IT; it++) {
        int i = tid + it*256;
        if (i < NP) p[i] = vals[it] * inv;
    }
}

// ---------------- im2col for tubelet conv (stride==kernel==(2,16,16)) ----------------
__global__ void im2col_kernel(const float* __restrict__ x)
{
    long long idx = (long long)blockIdx.x * 256 + threadIdx.x;
    if (idx >= (long long)NTOK * KPATCH) return;
    int j = (int)(idx % KPATCH);
    int m = (int)(idx / KPATCH);
    int b = m / NP, n = m % NP;
    int t = n / 196, r = n % 196, yy = r / 14, xx = r % 14;
    int i  = j / 512, r2 = j % 512;
    int dt = r2 / 256, r3 = r2 % 256;
    int dy = r3 / 16,  dx = r3 % 16;
    long long off = ((((long long)(b*3 + i)*16 + (2*t + dt))*224) + (16*yy + dy))*224 + (16*xx + dx);
    g_im2col[idx] = x[off];
}

// ---------------- positional encoding ----------------
__global__ void freq_kernel()
{
    int c2 = threadIdx.x;
    if (c2 < EMBED/2) g_freq[c2] = pow(10000.0, -2.0 * c2 / (double)EMBED);
}
__global__ void posadd_kernel()
{
    int idx = blockIdx.x * 256 + threadIdx.x;
    if (idx >= NP*EMBED) return;
    int n = idx / EMBED, c = idx % EMBED;
    double a = (double)n * g_freq[c >> 1];
    // double-precision range reduction, single-precision sin/cos (err ~1e-6)
    const double TWO_PI = 6.283185307179586476925286766559;
    int k = (int)(a * (1.0 / TWO_PI) + 0.5);
    float rf = (float)(a - (double)k * TWO_PI);
    float v = (c & 1) ? cosf(rf) : sinf(rf);
    g_h[idx]            += v;
    g_h[idx + NP*EMBED] += v;   // batch 1
}

// ---------------- mean pool over tokens ----------------
__global__ void pool_kernel()
{
    int idx = blockIdx.x * 256 + threadIdx.x;
    if (idx >= BATCH*EMBED) return;
    int b = idx / EMBED, c = idx % EMBED;
    const float* base = g_h + (long long)b*NP*EMBED + c;
    float s = 0.f;
    for (int n = 0; n < NP; n++) s += base[(long long)n*EMBED];
    g_pool[idx] = s * (1.0f / NP);
}

// ---------------- classifier head: one warp per (b, class) ----------------
__global__ void head_kernel(const float* __restrict__ W, const float* __restrict__ hb,
                            float* __restrict__ out)
{
    int g = blockIdx.x * 256 + threadIdx.x;
    int warp = g >> 5, lane = g & 31;
    if (warp >= BATCH*1000) return;
    int b = warp / 1000, j = warp % 1000;
    float s = 0.f;
    for (int c = lane; c < EMBED; c += 32)
        s += g_pln[b*EMBED + c] * W[j*EMBED + c];
    #pragma unroll
    for (int o = 16; o > 0; o >>= 1) s += __shfl_xor_sync(0xffffffffu, s, o);
    if (lane == 0) out[warp] = s + hb[j];
}

// ---------------- host orchestration ----------------
extern "C" void kernel_launch(void* const* d_in, const int* in_sizes, int n_in,
                              void* d_out, int out_size)
{
    const float* x      = (const float*)d_in[0];
    const float* conv_w = (const float*)d_in[1];
    const float* conv_b = (const float*)d_in[2];
    const float* n1s    = (const float*)d_in[3];
    const float* n1b    = (const float*)d_in[4];
    const float* qkv_w  = (const float*)d_in[5];
    const float* out_w  = (const float*)d_in[6];
    const float* out_b  = (const float*)d_in[7];
    const float* n2s    = (const float*)d_in[8];
    const float* n2b    = (const float*)d_in[9];
    const float* fc1_w  = (const float*)d_in[10];
    const float* fc1_b  = (const float*)d_in[11];
    const float* fc2_w  = (const float*)d_in[12];
    const float* fc2_b  = (const float*)d_in[13];
    const float* fns    = (const float*)d_in[14];
    const float* fnb    = (const float*)d_in[15];
    const float* head_w = (const float*)d_in[16];
    const float* head_b = (const float*)d_in[17];
    float* out = (float*)d_out;

    float *im2col, *h, *y, *qkv, *attn, *ao, *mlp, *pool, *pln;
    cudaGetSymbolAddress((void**)&im2col, g_im2col);
    cudaGetSymbolAddress((void**)&h,      g_h);
    cudaGetSymbolAddress((void**)&y,      g_y);
    cudaGetSymbolAddress((void**)&qkv,    g_qkv);
    cudaGetSymbolAddress((void**)&attn,   g_attn);
    cudaGetSymbolAddress((void**)&ao,     g_ao);
    cudaGetSymbolAddress((void**)&mlp,    g_mlp);
    cudaGetSymbolAddress((void**)&pool,   g_pool);
    cudaGetSymbolAddress((void**)&pln,    g_pln);

    const long long Z0 = 0;

    // ---- patch embed ----
    im2col_kernel<<<(int)(((long long)NTOK*KPATCH + 255)/256), 256>>>(x);
    {   // h = im2col @ conv_w^T + conv_b
        dim3 g((EMBED+63)/64, (NTOK+127)/128, 1);
        mma_gemm<1,true><<<g,256>>>(
            im2col, conv_w, conv_b, nullptr, h,
            NTOK, EMBED, KPATCH, KPATCH, KPATCH, EMBED, 0,
            Z0,Z0,Z0,Z0,Z0,Z0,Z0,Z0, 1);
    }
    freq_kernel<<<1, EMBED/2>>>();
    posadd_kernel<<<(NP*EMBED + 255)/256, 256>>>();

    // ---- transformer blocks ----
    for (int l = 0; l < DEPTH; l++) {
        const float* qw = qkv_w + (long long)l*3*EMBED*EMBED;
        const float* ow = out_w + (long long)l*EMBED*EMBED;
        const float* ob = out_b + (long long)l*EMBED;
        const float* w1 = fc1_w + (long long)l*MLPH*EMBED;
        const float* b1 = fc1_b + (long long)l*MLPH;
        const float* w2 = fc2_w + (long long)l*EMBED*MLPH;
        const float* b2 = fc2_b + (long long)l*EMBED;

        // y = LN1(h)
        ln_kernel<<<NTOK,256>>>(h, n1s + l*EMBED, n1b + l*EMBED, y, EMBED);

        // qkv = y @ qw^T
        {
            dim3 g((3*EMBED+63)/64, (NTOK+127)/128, 1);
            mma_gemm<0,true><<<g,256>>>(
                y, qw, nullptr, nullptr, qkv,
                NTOK, 3*EMBED, EMBED, EMBED, EMBED, 3*EMBED, 0,
                Z0,Z0,Z0,Z0,Z0,Z0,Z0,Z0, 1);
        }

        // S[b,h] = Q @ K^T   (M=N=1568, K=96), batched z = b*H + h
        {
            dim3 g((NP+63)/64, (NP+127)/128, BATCH*HEADS);
            mma_gemm<0,true><<<g,256>>>(
                qkv /*Q*/, qkv + EMBED /*K*/, nullptr, nullptr, attn,
                NP, NP, HDIM, 3*EMBED, 3*EMBED, NP, 0,
                (long long)NP*3*EMBED, (long long)HDIM,
                (long long)NP*3*EMBED, (long long)HDIM,
                (long long)HEADS*NP*NP, (long long)NP*NP,
                Z0, Z0, HEADS);
        }

        softmax_kernel<<<BATCH*HEADS*NP, 256>>>(attn);

        // O[b,h] = P @ V    (M=1568, N=96, K=1568), B in [K,N] layout
        {
            dim3 g((HDIM+63)/64, (NP+127)/128, BATCH*HEADS);
            mma_gemm<0,false><<<g,256>>>(
                attn, qkv + 2*EMBED /*V*/, nullptr, nullptr, ao,
                NP, HDIM, NP, NP, 3*EMBED, EMBED, 0,
                (long long)HEADS*NP*NP, (long long)NP*NP,
                (long long)NP*3*EMBED, (long long)HDIM,
                (long long)NP*EMBED, (long long)HDIM,
                Z0, Z0, HEADS);
        }

        // h = h + ao @ ow^T + ob
        {
            dim3 g((EMBED+63)/64, (NTOK+127)/128, 1);
            mma_gemm<4,true><<<g,256>>>(
                ao, ow, ob, h, h,
                NTOK, EMBED, EMBED, EMBED, EMBED, EMBED, EMBED,
                Z0,Z0,Z0,Z0,Z0,Z0,Z0,Z0, 1);
        }

        // y = LN2(h)
        ln_kernel<<<NTOK,256>>>(h, n2s + l*EMBED, n2b + l*EMBED, y, EMBED);

        // mlp = gelu(y @ w1^T + b1)
        {
            dim3 g((MLPH+63)/64, (NTOK+127)/128, 1);
            mma_gemm<2,true><<<g,256>>>(
                y, w1, b1, nullptr, mlp,
                NTOK, MLPH, EMBED, EMBED, EMBED, MLPH, 0,
                Z0,Z0,Z0,Z0,Z0,Z0,Z0,Z0, 1);
        }

        // h = h + mlp @ w2^T + b2
        {
            dim3 g((EMBED+63)/64, (NTOK+127)/128, 1);
            mma_gemm<4,true><<<g,256>>>(
                mlp, w2, b2, h, h,
                NTOK, EMBED, MLPH, MLPH, MLPH, EMBED, EMBED,
                Z0,Z0,Z0,Z0,Z0,Z0,Z0,Z0, 1);
        }
    }

    // ---- pooled head ----
    pool_kernel<<<(BATCH*EMBED + 255)/256, 256>>>();
    ln_kernel<<<BATCH,256>>>(pool, fns, fnb, pln, EMBED);
    head_kernel<<<(BATCH*1000*32 + 255)/256, 256>>>(head_w, head_b, out);
}